// round 2
// baseline (speedup 1.0000x reference)
#include <cuda_runtime.h>

#define DIMV 128
#define HIDV 128
#define BATCH 64

typedef unsigned long long ull;

// Compacted scratch (device globals: no allocation allowed)
__device__ float g_hq[BATCH * 64 * HIDV];  // compacted valid-n rows of q@W1[:128]+b1
__device__ float g_hd[BATCH * 64 * HIDV];  // compacted valid-m rows of d@W1[128:]
__device__ int   g_nidx[BATCH * 64];
__device__ int   g_midx[BATCH * 64];
__device__ int   g_ncnt[BATCH];
__device__ int   g_mcnt[BATCH];

// ---- f32x2 packed helpers ----
__device__ __forceinline__ ull pack2(float x, float y) {
    ull r; asm("mov.b64 %0, {%1,%2};" : "=l"(r) : "f"(x), "f"(y)); return r;
}
__device__ __forceinline__ void unpack2(ull v, float& x, float& y) {
    asm("mov.b64 {%0,%1}, %2;" : "=f"(x), "=f"(y) : "l"(v));
}
__device__ __forceinline__ ull fma2(ull a, ull b, ull c) {
    ull d; asm("fma.rn.f32x2 %0, %1, %2, %3;" : "=l"(d) : "l"(a), "l"(b), "l"(c)); return d;
}
__device__ __forceinline__ ull add2(ull a, ull b) {
    ull d; asm("add.rn.f32x2 %0, %1, %2;" : "=l"(d) : "l"(a), "l"(b)); return d;
}

// Mask dtype auto-detect: 0 = int32, 1 = uint8, 2 = float32
__device__ __forceinline__ bool mask_at(const void* p, int i, int mode) {
    if (mode == 0) return ((const int*)p)[i] != 0;
    if (mode == 2) return ((const float*)p)[i] != 0.0f;
    return ((const unsigned char*)p)[i] != 0;
}

// ============================================================================
// Setup: detect mask dtype once, build compacted index lists for all batches.
// 1 block, 256 threads. Warp w handles (b,side) jobs w, w+8, ...
// ============================================================================
__global__ void setup_kernel(const void* __restrict__ qmask,
                             const void* __restrict__ dmask)
{
    __shared__ int meta[2];  // [0]=notInt [1]=notF32
    const int tid = threadIdx.x, lane = tid & 31, wid = tid >> 5;
    if (tid < 2) meta[tid] = 0;
    __syncthreads();
    {
        const unsigned* qw = (const unsigned*)qmask;
        int notInt = 0, notF32 = 0;
        for (int i = tid; i < 512; i += 256) {
            unsigned w = qw[i];
            if (w > 1u) notInt = 1;
            if (w != 0u && w != 0x3F800000u) notF32 = 1;
        }
        if (notInt) meta[0] = 1;
        if (notF32) meta[1] = 1;
    }
    __syncthreads();
    const int mode = (meta[0] == 0) ? 0 : ((meta[1] == 0) ? 2 : 1);
    const unsigned lt = (1u << lane) - 1u;

    for (int job = wid; job < 2 * BATCH; job += 8) {
        const int b = job >> 1, side = job & 1;
        const void* mp = side ? dmask : qmask;
        bool v0 = mask_at(mp, b * 64 + lane, mode);
        bool v1 = mask_at(mp, b * 64 + 32 + lane, mode);
        unsigned m0 = __ballot_sync(0xFFFFFFFFu, v0);
        unsigned m1 = __ballot_sync(0xFFFFFFFFu, v1);
        int c0 = __popc(m0), cnt = c0 + __popc(m1);
        int* ilist = (side ? g_midx : g_nidx) + b * 64;
        if (v0) ilist[__popc(m0 & lt)] = lane;
        if (v1) ilist[c0 + __popc(m1 & lt)] = 32 + lane;
        if (lane == 0) {
            if (side) g_mcnt[b] = cnt; else g_ncnt[b] = cnt;
            if (cnt & 1) {  // pad list to even with duplicate of last valid
                int last = m1 ? (32 + 31 - __clz(m1)) : (31 - __clz(m0));
                ilist[cnt] = last;
            }
        }
    }
}

// ============================================================================
// Proj: compute hq/hd ONLY for valid (compacted) rows, stored compacted.
// grid = 128 = (b, side). 256 threads, thread tile 1 row x 16 h.
// Xs transposed [d][row] pad 69 (conflict-free), Ws [d][h] pad 132.
// ============================================================================
#define XPAD 69
#define WPAD 132

__global__ void __launch_bounds__(256)
proj_kernel(const float* __restrict__ query, const float* __restrict__ doc,
            const float* __restrict__ W1, const float* __restrict__ b1)
{
    extern __shared__ float sm[];
    float* Xs  = sm;                       // [128][XPAD]
    float* Ws  = sm + 128 * XPAD;          // [128][WPAD]
    float* bs  = Ws + 128 * WPAD;          // [128]
    int* idx_s = (int*)(bs + 128);         // [64]

    const int tid  = threadIdx.x;
    const int side = blockIdx.x & 1;
    const int b    = blockIdx.x >> 1;

    const int nv  = side ? g_mcnt[b] : g_ncnt[b];
    const int nvp = (nv + 1) & ~1;
    if (nvp == 0) return;

    const int* list = (side ? g_midx : g_nidx) + b * 64;
    if (tid < nvp) idx_s[tid] = list[tid];
    if (side == 0 && tid >= 128) bs[tid - 128] = b1[tid - 128];

    const float* Wg = W1 + side * DIMV * HIDV;
    for (int i = tid; i < 128 * 32; i += 256) {
        int d = i >> 5, seg = i & 31;
        *(float4*)(Ws + d * WPAD + seg * 4) = ((const float4*)Wg)[i];
    }
    __syncthreads();

    const float* X = (side ? doc : query) + b * 64 * DIMV;
    for (int i = tid; i < nvp * 32; i += 256) {
        int r = i >> 5, seg = i & 31;
        float4 v = ((const float4*)(X + idx_s[r] * DIMV))[seg];
        int d = seg * 4;
        Xs[(d + 0) * XPAD + r] = v.x;
        Xs[(d + 1) * XPAD + r] = v.y;
        Xs[(d + 2) * XPAD + r] = v.z;
        Xs[(d + 3) * XPAD + r] = v.w;
    }
    __syncthreads();

    const int hgrp = tid & 7, h0 = hgrp * 16;
    float* gbase = (side ? g_hd : g_hq) + b * 64 * HIDV;

    for (int r = tid >> 3; r < nvp; r += 32) {
        ull acc[8];
#pragma unroll
        for (int j = 0; j < 8; j++) acc[j] = 0ull;
        const float* wb = Ws + h0;
        const float* xb = Xs + r;
#pragma unroll 4
        for (int d = 0; d < 128; d++) {
            float x = xb[d * XPAD];
            ull xp = pack2(x, x);
            const ulonglong2* wr = (const ulonglong2*)(wb + d * WPAD);
            ulonglong2 wa = wr[0], wb2 = wr[1], wc = wr[2], wd = wr[3];
            acc[0] = fma2(xp, wa.x,  acc[0]);
            acc[1] = fma2(xp, wa.y,  acc[1]);
            acc[2] = fma2(xp, wb2.x, acc[2]);
            acc[3] = fma2(xp, wb2.y, acc[3]);
            acc[4] = fma2(xp, wc.x,  acc[4]);
            acc[5] = fma2(xp, wc.y,  acc[5]);
            acc[6] = fma2(xp, wd.x,  acc[6]);
            acc[7] = fma2(xp, wd.y,  acc[7]);
        }
        float v[16];
#pragma unroll
        for (int j = 0; j < 8; j++) unpack2(acc[j], v[2 * j], v[2 * j + 1]);
        if (side == 0) {
#pragma unroll
            for (int k = 0; k < 16; k++) v[k] += bs[h0 + k];
        }
        float* go = gbase + r * HIDV + h0;
#pragma unroll
        for (int q = 0; q < 4; q++)
            *(float4*)(go + q * 4) =
                make_float4(v[4 * q], v[4 * q + 1], v[4 * q + 2], v[4 * q + 3]);
    }
}

// ============================================================================
// Pair: grid = B*4 = 256 blocks. Block (b, qtr) handles the qtr-th even-sized
// chunk of the COMPACTED valid-m list (<=16 rows) x all valid n (<=64).
// 2n x 2m register tiles, packed f32x2. Output pre-zeroed by memset.
// ============================================================================
__global__ void __launch_bounds__(128)
pair_kernel(const float* __restrict__ W2g, const float* __restrict__ b2g,
            float* __restrict__ out)
{
    extern __shared__ float sm[];
    float* hq_s = sm;                       // [64][132]
    float* hd_s = hq_s + 64 * 132;          // [16][132]
    float* w2_s = hd_s + 16 * 132;          // [3][128]
    int* nlist  = (int*)(w2_s + 384);       // 64
    int* mlist  = nlist + 64;               // 16

    const int tid = threadIdx.x;
    const int b   = blockIdx.x >> 2;
    const int qtr = blockIdx.x & 3;

    const int nv = g_ncnt[b], mv = g_mcnt[b];
    if (nv == 0 || mv == 0) return;

    const int chunk  = (((mv + 3) >> 2) + 1) & ~1;  // even, 4*chunk >= mv
    const int mstart = qtr * chunk;
    if (mstart >= mv) return;
    const int mc  = min(chunk, mv - mstart);
    const int mvp = (mc + 1) & ~1;                  // padded rows exist globally
    const int nvp = (nv + 1) & ~1;

    if (tid < nvp) nlist[tid] = g_nidx[b * 64 + tid];
    if (tid >= 64 && tid < 64 + mvp) mlist[tid - 64] = g_midx[b * 64 + mstart + tid - 64];
    for (int i = tid; i < 384; i += 128) {  // W2 (128,3) -> [o][h]
        int h = i / 3, o = i - h * 3;
        w2_s[o * 128 + h] = W2g[i];
    }
    const float* hqg = g_hq + b * 64 * HIDV;
    for (int i = tid; i < nvp * 32; i += 128) {
        int r = i >> 5, seg = i & 31;
        *(float4*)(hq_s + r * 132 + seg * 4) = ((const float4*)(hqg + r * HIDV))[seg];
    }
    const float* hdg = g_hd + (b * 64 + mstart) * HIDV;
    for (int i = tid; i < mvp * 32; i += 128) {
        int r = i >> 5, seg = i & 31;
        *(float4*)(hd_s + r * 132 + seg * 4) = ((const float4*)(hdg + r * HIDV))[seg];
    }
    __syncthreads();

    const float b2_0 = b2g[0], b2_1 = b2g[1], b2_2 = b2g[2];
    const int ntiles = nvp >> 1, mtiles = mvp >> 1;
    const int total = ntiles * mtiles;

    for (int t = tid; t < total; t += 128) {
        int ni = t / mtiles;
        int mi = t - ni * mtiles;
        const float* pa0 = hq_s + (2 * ni) * 132;
        const float* pa1 = pa0 + 132;
        const float* pd0 = hd_s + (2 * mi) * 132;
        const float* pd1 = pd0 + 132;

        ull acc[4][3];
#pragma unroll
        for (int c = 0; c < 4; c++)
#pragma unroll
            for (int o = 0; o < 3; o++) acc[c][o] = 0ull;

#define COMBO(c, Alo, Ahi, Dlo, Dhi) do {                                   \
            ull tlo = add2((Alo), (Dlo));                                    \
            ull thi = add2((Ahi), (Dhi));                                    \
            float f0, f1, f2, f3;                                            \
            unpack2(tlo, f0, f1); unpack2(thi, f2, f3);                      \
            f0 = fmaxf(f0, 0.f); f1 = fmaxf(f1, 0.f);                        \
            f2 = fmaxf(f2, 0.f); f3 = fmaxf(f3, 0.f);                        \
            tlo = pack2(f0, f1); thi = pack2(f2, f3);                        \
            acc[c][0] = fma2(tlo, w0.x, acc[c][0]);                          \
            acc[c][0] = fma2(thi, w0.y, acc[c][0]);                          \
            acc[c][1] = fma2(tlo, w1.x, acc[c][1]);                          \
            acc[c][1] = fma2(thi, w1.y, acc[c][1]);                          \
            acc[c][2] = fma2(tlo, w2v.x, acc[c][2]);                         \
            acc[c][2] = fma2(thi, w2v.y, acc[c][2]);                         \
        } while (0)

#pragma unroll 4
        for (int h = 0; h < 128; h += 4) {
            ulonglong2 A0 = *(const ulonglong2*)(pa0 + h);
            ulonglong2 A1 = *(const ulonglong2*)(pa1 + h);
            ulonglong2 D0 = *(const ulonglong2*)(pd0 + h);
            ulonglong2 D1 = *(const ulonglong2*)(pd1 + h);
            ulonglong2 w0  = *(const ulonglong2*)(w2_s + h);
            ulonglong2 w1  = *(const ulonglong2*)(w2_s + 128 + h);
            ulonglong2 w2v = *(const ulonglong2*)(w2_s + 256 + h);
            COMBO(0, A0.x, A0.y, D0.x, D0.y);
            COMBO(1, A0.x, A0.y, D1.x, D1.y);
            COMBO(2, A1.x, A1.y, D0.x, D0.y);
            COMBO(3, A1.x, A1.y, D1.x, D1.y);
        }
#undef COMBO

        const int gn0 = nlist[2 * ni], gn1 = nlist[2 * ni + 1];
        const int gm0 = mlist[2 * mi], gm1 = mlist[2 * mi + 1];

#define WRITE(c, gn, gm) do {                                               \
            float lo, hi, s0, s1, s2;                                        \
            unpack2(acc[c][0], lo, hi); s0 = lo + hi + b2_0;                 \
            unpack2(acc[c][1], lo, hi); s1 = lo + hi + b2_1;                 \
            unpack2(acc[c][2], lo, hi); s2 = lo + hi + b2_2;                 \
            float* po = out + (((b * 64 + (gn)) * 64 + (gm)) * 3);           \
            po[0] = s0; po[1] = s1; po[2] = s2;                              \
        } while (0)

        WRITE(0, gn0, gm0);
        WRITE(1, gn0, gm1);
        WRITE(2, gn1, gm0);
        WRITE(3, gn1, gm1);
#undef WRITE
    }
}

// ============================================================================
extern "C" void kernel_launch(void* const* d_in, const int* in_sizes, int n_in,
                              void* d_out, int out_size)
{
    const float* query = (const float*)d_in[0];
    const float* doc   = (const float*)d_in[1];
    const void*  qmask = d_in[2];
    const void*  dmask = d_in[3];
    const float* W1    = (const float*)d_in[4];
    const float* b1    = (const float*)d_in[5];
    const float* W2    = (const float*)d_in[6];
    const float* b2    = (const float*)d_in[7];
    float* out = (float*)d_out;

    const int sm1 = (128 * XPAD + 128 * WPAD + 128) * (int)sizeof(float)
                    + 64 * (int)sizeof(int);                                // ~103.9 KB
    const int sm2 = (64 * 132 + 16 * 132 + 384) * (int)sizeof(float)
                    + 80 * (int)sizeof(int);                                // ~44 KB

    cudaFuncSetAttribute(proj_kernel, cudaFuncAttributeMaxDynamicSharedMemorySize, sm1);
    cudaFuncSetAttribute(pair_kernel, cudaFuncAttributeMaxDynamicSharedMemorySize, sm2);

    setup_kernel<<<1, 256>>>(qmask, dmask);
    proj_kernel<<<128, 256, sm1>>>(query, doc, W1, b1);
    cudaMemsetAsync(out, 0, (size_t)out_size * sizeof(float), 0);
    pair_kernel<<<256, 128, sm2>>>(W2, b2, out);
}